// round 1
// baseline (speedup 1.0000x reference)
#include <cuda_runtime.h>
#include <float.h>

// ChessMoveSelector — algebraically collapsed.
// probs[b,n] = mask * softmax_n( moves[b,n,0]*w0 + moves[b,n,1]*w1 )
// where w = move_w^T @ comb_w[0, BD:].  All batch-constant terms (entire
// conv/fc board branch, biases) cancel inside the row softmax.
//
// Inputs (metadata order):
//  0 board, 1 extra, 2 moves(B,64,2), 3 lengths(B), 4..11 conv/fc params,
//  12 move_w(128,2), 13 move_b, 14 comb_w(1,384), 15 comb_b
// Output: probs (B,64) float32.

#define NMAX 64
#define MD 128
#define BD 256

__global__ void chess_move_softmax_kernel(
    const float* __restrict__ moves,   // [B, 64, 2]
    const int*   __restrict__ lengths, // [B]
    const float* __restrict__ move_w,  // [128, 2]
    const float* __restrict__ comb_w,  // [1, 384]
    float* __restrict__ out,           // [B, 64]
    int B)
{
    __shared__ float sw[2];

    // Warp 0 computes the collapsed 2-vector w = move_w^T @ comb_w[0, BD:]
    if (threadIdx.x < 32) {
        float s0 = 0.f, s1 = 0.f;
        #pragma unroll
        for (int m = threadIdx.x; m < MD; m += 32) {
            float wm = comb_w[BD + m];
            s0 += wm * move_w[2 * m + 0];
            s1 += wm * move_w[2 * m + 1];
        }
        #pragma unroll
        for (int off = 16; off > 0; off >>= 1) {
            s0 += __shfl_down_sync(0xFFFFFFFFu, s0, off);
            s1 += __shfl_down_sync(0xFFFFFFFFu, s1, off);
        }
        if (threadIdx.x == 0) { sw[0] = s0; sw[1] = s1; }
    }
    __syncthreads();

    const float w0 = sw[0];
    const float w1 = sw[1];

    // One warp per batch row; each lane handles 2 moves.
    const int warps_per_block = blockDim.x >> 5;
    const int row  = blockIdx.x * warps_per_block + (threadIdx.x >> 5);
    const int lane = threadIdx.x & 31;
    if (row >= B) return;

    const int len = lengths[row];

    // moves row = 64*2 floats = 512B contiguous; lane loads one float4 (2 moves)
    const float4 mv = reinterpret_cast<const float4*>(moves + (size_t)row * NMAX * 2)[lane];

    const int n0 = 2 * lane;
    const int n1 = 2 * lane + 1;
    const bool v0 = n0 < len;
    const bool v1 = n1 < len;

    const float s0 = mv.x * w0 + mv.y * w1;
    const float s1 = mv.z * w0 + mv.w * w1;

    // Row max over valid entries (len >= 1 guaranteed)
    float mx = fmaxf(v0 ? s0 : -FLT_MAX, v1 ? s1 : -FLT_MAX);
    #pragma unroll
    for (int off = 16; off > 0; off >>= 1)
        mx = fmaxf(mx, __shfl_xor_sync(0xFFFFFFFFu, mx, off));

    const float e0 = v0 ? expf(s0 - mx) : 0.f;
    const float e1 = v1 ? expf(s1 - mx) : 0.f;

    float sum = e0 + e1;
    #pragma unroll
    for (int off = 16; off > 0; off >>= 1)
        sum += __shfl_xor_sync(0xFFFFFFFFu, sum, off);

    const float inv = 1.0f / sum;
    float2 r;
    r.x = e0 * inv;
    r.y = e1 * inv;
    reinterpret_cast<float2*>(out + (size_t)row * NMAX)[lane] = r;
}

extern "C" void kernel_launch(void* const* d_in, const int* in_sizes, int n_in,
                              void* d_out, int out_size)
{
    const float* moves   = (const float*)d_in[2];
    const int*   lengths = (const int*)d_in[3];
    const float* move_w  = (const float*)d_in[12];
    const float* comb_w  = (const float*)d_in[14];
    float* out = (float*)d_out;

    const int B = in_sizes[3];            // number of batch rows
    const int threads = 256;              // 8 warps -> 8 rows per block
    const int rows_per_block = threads / 32;
    const int blocks = (B + rows_per_block - 1) / rows_per_block;

    chess_move_softmax_kernel<<<blocks, threads>>>(moves, lengths, move_w, comb_w, out, B);
}

// round 4
// speedup vs baseline: 1.0207x; 1.0207x over previous
#include <cuda_runtime.h>
#include <float.h>

// ChessMoveSelector — algebraically collapsed.
// probs[b,n] = mask * softmax_n( moves[b,n,0]*w0 + moves[b,n,1]*w1 )
// where w = move_w^T @ comb_w[0, BD:].  All batch-constant terms (entire
// conv/fc board branch, biases) cancel inside the row softmax.
//
// Round 4 (= Round 3 resubmit after infra failure): latency-optimized for
// plain sm_100: per-warp w (no smem/sync), front-batched global loads,
// redux.sync.max.s32 via monotone float->int map, butterfly shuffles for
// sums, __expf.

#define NMAX 64
#define MD 128
#define BD 256

// Order-preserving float <-> int monotone mapping for integer max reduction.
__device__ __forceinline__ int f32_to_ordered_s32(float f) {
    int i = __float_as_int(f);
    return (i < 0) ? (i ^ 0x7fffffff) : i;   // now s32 compare == fp32 compare
}

__device__ __forceinline__ float warp_max_f32(float v) {
    int key = f32_to_ordered_s32(v);
    int r;
    asm volatile("redux.sync.max.s32 %0, %1, 0xffffffff;" : "=r"(r) : "r"(key));
    r = (r < 0) ? (r ^ 0x7fffffff) : r;      // invert mapping
    return __int_as_float(r);
}

__device__ __forceinline__ float warp_sum_f32(float v) {
    #pragma unroll
    for (int off = 16; off > 0; off >>= 1)
        v += __shfl_xor_sync(0xffffffffu, v, off);
    return v;
}

__global__ void chess_move_softmax_kernel(
    const float4* __restrict__ moves4,  // [B*32] float4 == [B,64,2] floats
    const int*    __restrict__ lengths, // [B]
    const float2* __restrict__ move_w2, // [128] float2 == move_w[128,2]
    const float*  __restrict__ comb_w,  // [384]
    float2*       __restrict__ out2,    // [B*32] float2 == probs[B,64]
    int B)
{
    const int warp = (blockIdx.x * blockDim.x + threadIdx.x) >> 5;
    const int lane = threadIdx.x & 31;
    if (warp >= B) return;

    // ---- Issue ALL global loads up front so DRAM latencies overlap ----
    const int    len = lengths[warp];
    const float4 mv  = moves4[(size_t)warp * 32 + lane];   // 2 moves for this lane

    float cw[4];
    float2 mw[4];
    #pragma unroll
    for (int i = 0; i < 4; i++) {
        const int m = lane + i * 32;
        cw[i] = comb_w[BD + m];
        mw[i] = move_w2[m];
    }

    // ---- Per-warp collapsed weight vector w = move_w^T @ comb_w[BD:] ----
    float s0 = 0.f, s1 = 0.f;
    #pragma unroll
    for (int i = 0; i < 4; i++) {
        s0 = fmaf(cw[i], mw[i].x, s0);
        s1 = fmaf(cw[i], mw[i].y, s1);
    }
    // Two independent butterfly chains — latencies interleave.
    #pragma unroll
    for (int off = 16; off > 0; off >>= 1) {
        s0 += __shfl_xor_sync(0xffffffffu, s0, off);
        s1 += __shfl_xor_sync(0xffffffffu, s1, off);
    }
    const float w0 = s0;
    const float w1 = s1;

    // ---- Scores for this lane's 2 moves ----
    const int  n0 = 2 * lane;
    const bool v0 = (n0     < len);
    const bool v1 = (n0 + 1 < len);

    const float sc0 = fmaf(mv.x, w0, mv.y * w1);
    const float sc1 = fmaf(mv.z, w0, mv.w * w1);

    // ---- Masked softmax over the 64 moves of this row ----
    const float mx = warp_max_f32(fmaxf(v0 ? sc0 : -FLT_MAX,
                                        v1 ? sc1 : -FLT_MAX));

    const float e0 = v0 ? __expf(sc0 - mx) : 0.f;
    const float e1 = v1 ? __expf(sc1 - mx) : 0.f;

    const float inv = __frcp_rn(warp_sum_f32(e0 + e1));

    float2 r;
    r.x = e0 * inv;
    r.y = e1 * inv;
    out2[(size_t)warp * 32 + lane] = r;
}

extern "C" void kernel_launch(void* const* d_in, const int* in_sizes, int n_in,
                              void* d_out, int out_size)
{
    const float4* moves   = (const float4*)d_in[2];
    const int*    lengths = (const int*)d_in[3];
    const float2* move_w  = (const float2*)d_in[12];
    const float*  comb_w  = (const float*)d_in[14];
    float2* out = (float2*)d_out;

    const int B = in_sizes[3];                 // 4096 rows
    const int threads = 512;                   // 16 warps -> 16 rows per block
    const int warps_per_block = threads / 32;
    const int blocks = (B + warps_per_block - 1) / warps_per_block;

    chess_move_softmax_kernel<<<blocks, threads>>>(moves, lengths, move_w, comb_w, out, B);
}